// round 1
// baseline (speedup 1.0000x reference)
#include <cuda_runtime.h>
#include <cstdint>

#define BATCH 16
#define NANCH 25200
#define NCLS  80
#define TOPK  2048
#define CAND  4096
#define MASKW 32   // 2048 bits / 64

// ---------------- scratch (no allocations allowed) ----------------
__device__ float              g_scores[BATCH * NANCH];
__device__ int                g_labels[BATCH * NANCH];
__device__ float              g_top_scores[BATCH * TOPK];
__device__ float4             g_top_boxes[BATCH * TOPK];
__device__ int                g_top_labels[BATCH * TOPK];
__device__ unsigned long long g_mask[(size_t)BATCH * TOPK * MASKW]; // pred masks (j<i), 8MB

// ---------------- Stage 1: per-anchor max/argmax over classes ----------------
// warp-per-row: coalesced 80-float row reads, shfl reduce with first-occurrence tie-break.
__global__ __launch_bounds__(256) void k_scores(const float* __restrict__ obj,
                                                const float* __restrict__ cls)
{
    int gwarp = (blockIdx.x * blockDim.x + threadIdx.x) >> 5;
    int lane  = threadIdx.x & 31;
    if (gwarp >= BATCH * NANCH) return;
    const float* p = cls + (size_t)gwarp * NCLS;

    float best = -1.0f; int bi = 0;
    #pragma unroll
    for (int k = lane; k < NCLS; k += 32) {
        float v = p[k];
        if (v > best) { best = v; bi = k; }  // ascending k -> first occurrence kept
    }
    #pragma unroll
    for (int off = 16; off; off >>= 1) {
        float ov = __shfl_down_sync(0xFFFFFFFFu, best, off);
        int   oi = __shfl_down_sync(0xFFFFFFFFu, bi,   off);
        if (ov > best || (ov == best && oi < bi)) { best = ov; bi = oi; }
    }
    if (lane == 0) {
        float s = obj[gwarp] * best;          // == max(obj*p) bitwise (monotone rounding)
        g_scores[gwarp] = (s > 0.25f) ? s : 0.0f;  // conf filter
        g_labels[gwarp] = bi;
    }
}

// ---------------- Stage 2: per-image radix-select + exact top-k sort ----------------
__global__ __launch_bounds__(1024) void k_select(const float4* __restrict__ boxes)
{
    __shared__ int                s_hist[256];
    __shared__ unsigned           s_prefix;
    __shared__ int                s_remaining;
    __shared__ int                s_cnt;
    __shared__ unsigned long long s_arr[CAND];  // 32KB

    const int b   = blockIdx.x;
    const int tid = threadIdx.x;
    const float* sc = g_scores + b * NANCH;

    if (tid == 0) { s_prefix = 0; s_remaining = TOPK; }

    // 4-pass MSD radix select on float-as-uint (all scores >= 0 -> order-preserving)
    const int iters = (NANCH + 1023) / 1024;
    for (int byte = 3; byte >= 0; --byte) {
        if (tid < 256) s_hist[tid] = 0;
        __syncthreads();
        unsigned prefix = s_prefix;
        int shift = byte * 8;
        for (int it = 0; it < iters; ++it) {
            int i = tid + it * 1024;
            bool ok = false; unsigned bin = 0;
            if (i < NANCH) {
                unsigned k = __float_as_uint(sc[i]);
                ok  = (byte == 3) || ((k >> (shift + 8)) == prefix);
                bin = (k >> shift) & 255u;
            }
            unsigned tag = ok ? bin : 0x100u;
            unsigned m = __match_any_sync(0xFFFFFFFFu, tag);
            int leader = __ffs(m) - 1;
            if (ok && (tid & 31) == leader) atomicAdd(&s_hist[bin], __popc(m));
        }
        __syncthreads();
        if (tid == 0) {
            int acc = 0, rem = s_remaining; unsigned sel = 0;
            for (int v = 255; v >= 0; --v) {
                int h = s_hist[v];
                if (acc + h >= rem) { sel = (unsigned)v; s_remaining = rem - acc; break; }
                acc += h;
            }
            s_prefix = (s_prefix << 8) | sel;
        }
        __syncthreads();
    }

    if (tid == 0) s_cnt = 0;
    __syncthreads();
    const unsigned T = s_prefix;  // key of the TOPK-th largest score

    // gather candidates: key > T always; key == T only if T>0 (T==0 padding is all-zero output anyway)
    for (int i = tid; i < NANCH; i += 1024) {
        unsigned k = __float_as_uint(sc[i]);
        bool take = (k > T) || (k == T && T > 0);
        if (take) {
            int p = atomicAdd(&s_cnt, 1);
            if (p < CAND)
                s_arr[p] = ((unsigned long long)k << 32) | (unsigned)(0xFFFFFFFFu - (unsigned)i);
        }
    }
    __syncthreads();
    int cnt = s_cnt; if (cnt > CAND) cnt = CAND;
    for (int p = cnt + tid; p < CAND; p += 1024) s_arr[p] = 0ull;
    __syncthreads();

    // bitonic sort descending on combined key (score desc, idx asc) -> matches lax.top_k exactly
    for (int kk = 2; kk <= CAND; kk <<= 1) {
        for (int j = kk >> 1; j > 0; j >>= 1) {
            for (int m = tid; m < CAND; m += 1024) {
                int l = m ^ j;
                if (l > m) {
                    unsigned long long a = s_arr[m], c = s_arr[l];
                    bool desc = ((m & kk) == 0);
                    if (desc ? (a < c) : (a > c)) { s_arr[m] = c; s_arr[l] = a; }
                }
            }
            __syncthreads();
        }
    }

    // emit sorted top-K intermediates (+ gather boxes/labels)
    for (int j = tid; j < TOPK; j += 1024) {
        unsigned long long c = s_arr[j];
        unsigned key = (unsigned)(c >> 32);
        int o = b * TOPK + j;
        g_top_scores[o] = __uint_as_float(key);
        if (key) {
            unsigned idx = 0xFFFFFFFFu - (unsigned)(c & 0xFFFFFFFFull);
            g_top_boxes[o]  = boxes[(size_t)b * NANCH + idx];
            g_top_labels[o] = g_labels[b * NANCH + idx];
        } else {
            g_top_boxes[o]  = make_float4(0.f, 0.f, 0.f, 0.f);
            g_top_labels[o] = 0;
        }
    }
}

// ---------------- Stage 3a: predecessor IoU bitmask (j < i, iou > 0.45) ----------------
__global__ __launch_bounds__(256) void k_mask()
{
    __shared__ float4 sbox[TOPK];   // 32KB
    __shared__ float  sarea[TOPK];  // 8KB
    const int b   = blockIdx.y;
    const int tid = threadIdx.x;
    for (int j = tid; j < TOPK; j += 256) {
        float4 v = g_top_boxes[b * TOPK + j];
        sbox[j]  = v;
        sarea[j] = (v.z - v.x) * (v.w - v.y);   // same op order as reference
    }
    __syncthreads();

    const int warp = tid >> 5, lane = tid & 31;
    const int i = blockIdx.x * 8 + warp;
    const float4 bi = sbox[i];
    const float  ai = sarea[i];

    unsigned long long word = 0ull;
    int j0   = lane * 64;
    int jend = min(j0 + 64, i);   // predecessors only
    for (int j = j0; j < jend; ++j) {
        float4 bj = sbox[j];
        float ltx = fmaxf(bi.x, bj.x);
        float lty = fmaxf(bi.y, bj.y);
        float rbx = fminf(bi.z, bj.z);
        float rby = fminf(bi.w, bj.w);
        float w = rbx - ltx, h = rby - lty;
        if (w > 0.0f && h > 0.0f) {             // else inter==0 -> iou==0, bit clear
            float inter = w * h;
            float denom = (ai + sarea[j]) - inter;
            float iou = __fdiv_rn(inter, denom); // IEEE div regardless of fast-math
            if (iou > 0.45f) word |= 1ull << (j & 63);
        }
    }
    g_mask[((size_t)b * TOPK + i) * MASKW + lane] = word;
}

// ---------------- Stage 3b: wavefront keep resolution + final output ----------------
// keep[i] = keep0[i] && no predecessor j with keep[j] (exact greedy-NMS fixed point on a DAG)
__global__ __launch_bounds__(1024) void k_nms(float* __restrict__ out_boxes,
                                              float* __restrict__ out_scores,
                                              float* __restrict__ out_labels)
{
    __shared__ unsigned long long resL[MASKW], keepL[MASKW], resS[MASKW], keepS[MASKW], keep0[MASKW];
    __shared__ int n_res;
    const int b = blockIdx.x, tid = threadIdx.x;

    if (tid < MASKW) { resL[tid] = 0ull; keepL[tid] = 0ull; keep0[tid] = 0ull; }
    if (tid == 0) n_res = 0;
    __syncthreads();
    for (int j = tid; j < TOPK; j += 1024)
        if (g_top_scores[b * TOPK + j] > 0.0f)
            atomicOr(&keep0[j >> 6], 1ull << (j & 63));
    __syncthreads();

    for (int round = 0; round < 4096; ++round) {
        if (tid < MASKW) { resS[tid] = resL[tid]; keepS[tid] = keepL[tid]; }
        __syncthreads();
        int done = n_res;      // uniform after barrier
        if (done >= TOPK) break;
        for (int i = tid; i < TOPK; i += 1024) {
            if (!((resS[i >> 6] >> (i & 63)) & 1ull)) {
                const unsigned long long* row = &g_mask[((size_t)b * TOPK + i) * MASKW];
                unsigned long long pend = 0ull, sup = 0ull;
                #pragma unroll
                for (int w = 0; w < MASKW; ++w) {
                    unsigned long long r = row[w];
                    pend |= r & ~resS[w];
                    sup  |= r &  keepS[w];
                }
                if (pend == 0ull) {  // all predecessors resolved in snapshot
                    bool kv = (((keep0[i >> 6] >> (i & 63)) & 1ull) != 0ull) && (sup == 0ull);
                    if (kv) atomicOr(&keepL[i >> 6], 1ull << (i & 63));
                    atomicOr(&resL[i >> 6], 1ull << (i & 63));
                    atomicAdd(&n_res, 1);
                }
            }
        }
        __syncthreads();
    }
    __syncthreads();

    // outputs: boxes [B,K,4], scores [B,K], labels [B,K] (as float), suppressed -> 0
    for (int j = tid; j < TOPK; j += 1024) {
        int o = b * TOPK + j;
        bool kp = ((keepL[j >> 6] >> (j & 63)) & 1ull) != 0ull;
        float f = kp ? 1.0f : 0.0f;
        float4 bx = g_top_boxes[o];
        out_boxes[o * 4 + 0] = bx.x * f;
        out_boxes[o * 4 + 1] = bx.y * f;
        out_boxes[o * 4 + 2] = bx.z * f;
        out_boxes[o * 4 + 3] = bx.w * f;
        out_scores[o] = kp ? g_top_scores[o] : 0.0f;
        out_labels[o] = kp ? (float)g_top_labels[o] : 0.0f;
    }
}

// ---------------- launch ----------------
extern "C" void kernel_launch(void* const* d_in, const int* in_sizes, int n_in,
                              void* d_out, int out_size)
{
    const float* boxes = (const float*)d_in[0];   // [16,25200,4]
    const float* obj   = (const float*)d_in[1];   // [16,25200]
    const float* cls   = (const float*)d_in[2];   // [16,25200,80]
    float* out = (float*)d_out;                    // boxes | scores | labels (float)

    (void)in_sizes; (void)n_in; (void)out_size;

    int rows = BATCH * NANCH;
    int blocks1 = (rows * 32 + 255) / 256;         // warp per row
    k_scores<<<blocks1, 256>>>(obj, cls);

    k_select<<<BATCH, 1024>>>((const float4*)boxes);

    dim3 gm(TOPK / 8, BATCH);
    k_mask<<<gm, 256>>>();

    float* out_boxes  = out;
    float* out_scores = out + (size_t)BATCH * TOPK * 4;
    float* out_labels = out + (size_t)BATCH * TOPK * 5;
    k_nms<<<BATCH, 1024>>>(out_boxes, out_scores, out_labels);
}